// round 9
// baseline (speedup 1.0000x reference)
#include <cuda_runtime.h>
#include <cuda_bf16.h>
#include <math.h>

// SimpleGNN: bucket scatter + tensor-core (tf32 mma) fused agg/MLP with
// in-kernel finalize. Self-cleaning state: __device__ globals start zeroed
// (module load); fused kernel re-zeros cursors (after reading deg) and the
// last block re-zeros hsum/done, so every graph replay sees clean scratch
// without a dedicated zero kernel. 2 launches total.
//
// Inputs: x[N*16] f32, edge_index int32 (harness downcast), W1,b1,W2,b2,Wh,bh.
// Output: 1 f32.

#define MAX_NODES 100000
#define CAP       128
#define HID       64
#define IN_DIM    16
#define TB        128          // threads per block (4 warps)
#define GRID_BLOCKS 592        // ~4 blocks/SM
#define TILE      16           // nodes per warp-tile
#define W_STRIDE  72           // conflict-free B-frag rows
#define H_STRIDE  68
#define V_STRIDE  17

__device__ unsigned g_cursor[MAX_NODES];          // zero-init at load
__device__ int      g_bucket[MAX_NODES * CAP];
__device__ float    g_hsum[HID];                  // zero-init at load
__device__ unsigned g_done;                       // zero-init at load

__device__ __forceinline__ unsigned f2tf32(float f) {
    unsigned r; asm("cvt.rna.tf32.f32 %0, %1;" : "=r"(r) : "f"(f)); return r;
}

__device__ __forceinline__ void mma_tf32(float& d0, float& d1, float& d2, float& d3,
                                         unsigned a0, unsigned a1, unsigned a2, unsigned a3,
                                         unsigned b0, unsigned b1) {
    asm volatile(
        "mma.sync.aligned.m16n8k8.row.col.f32.tf32.tf32.f32 "
        "{%0,%1,%2,%3}, {%4,%5,%6,%7}, {%8,%9}, {%0,%1,%2,%3};"
        : "+f"(d0), "+f"(d1), "+f"(d2), "+f"(d3)
        : "r"(a0), "r"(a1), "r"(a2), "r"(a3), "r"(b0), "r"(b1));
}

// ---------------------------------------------------------------------------
// Scatter: 4 edges per thread; cursor atomic doubles as degree counter.
// ---------------------------------------------------------------------------
__global__ void scatter_kernel(const int* __restrict__ ei, int E, int n) {
    int t = blockIdx.x * blockDim.x + threadIdx.x;
    int base = t * 4;
    if (base >= E) return;
    int4 s4 = *(const int4*)(ei + base);
    int4 d4 = *(const int4*)(ei + E + base);
#pragma unroll
    for (int j = 0; j < 4; j++) {
        int s = (j == 0) ? s4.x : (j == 1) ? s4.y : (j == 2) ? s4.z : s4.w;
        int d = (j == 0) ? d4.x : (j == 1) ? d4.y : (j == 2) ? d4.z : d4.w;
        if ((unsigned)s < (unsigned)n) {
            unsigned slot = atomicAdd(&g_cursor[s], 1u);
            if (slot < CAP) g_bucket[(size_t)s * CAP + slot] = d;
        }
    }
}

// ---------------------------------------------------------------------------
// Fused aggregation + MMA MLP + last-block finalize + state cleanup.
// ---------------------------------------------------------------------------
__global__ void __launch_bounds__(TB) fused_kernel(
    const float* __restrict__ x,
    const float* __restrict__ W1, const float* __restrict__ b1,
    const float* __restrict__ W2, const float* __restrict__ b2,
    const float* __restrict__ Wh, const float* __restrict__ bh,
    float* __restrict__ out, int n) {
    __shared__ unsigned sW1t[IN_DIM * W_STRIDE];
    __shared__ unsigned sW2t[HID * W_STRIDE];
    __shared__ float sb1[HID];
    __shared__ float sb2[HID];
    __shared__ unsigned sv[4][TILE * V_STRIDE];
    __shared__ unsigned sh1[4][TILE * H_STRIDE];
    __shared__ float ssum[HID];
    __shared__ int slast;

    int tid  = threadIdx.x;
    int wid  = tid >> 5;
    int lane = tid & 31;
    int g    = lane >> 2;     // mma groupID (row)
    int tg   = lane & 3;      // mma threadID_in_group

    for (int i = tid; i < IN_DIM * HID; i += TB) {
        int k = i >> 6, nn = i & 63;
        sW1t[k * W_STRIDE + nn] = f2tf32(W1[i]);
    }
    for (int i = tid; i < HID * HID; i += TB) {
        int k = i >> 6, nn = i & 63;
        sW2t[k * W_STRIDE + nn] = f2tf32(W2[i]);
    }
    if (tid < HID) { sb1[tid] = b1[tid]; sb2[tid] = b2[tid]; ssum[tid] = 0.0f; }
    __syncthreads();

    unsigned* svw = sv[wid];
    unsigned* shw = sh1[wid];
    float macc[16];
#pragma unroll
    for (int i = 0; i < 16; i++) macc[i] = 0.0f;

    for (int base = (blockIdx.x * 4 + wid) * TILE; base < n;
         base += GRID_BLOCKS * 4 * TILE) {

        // ---- aggregate 16 nodes (4-lane teams: lane tg reads float4 #tg of
        //      row d; one warp gather instr covers 8 distinct rows) ----
        for (int nl = 0; nl < TILE; nl++) {
            int node = base + nl;
            if (node < n) {
                unsigned deg = g_cursor[node];
                if (lane == 0) g_cursor[node] = 0u;   // self-clean for next replay
                unsigned lim = (deg < CAP) ? deg : CAP;
                const int* bucket = g_bucket + (size_t)node * CAP;
                float4 acc = make_float4(0.f, 0.f, 0.f, 0.f);
                for (unsigned i = (unsigned)g; i < lim; i += 8) {
                    int d = bucket[i];
                    float4 val = ((const float4*)(x + (size_t)d * IN_DIM))[tg];
                    acc.x += val.x; acc.y += val.y; acc.z += val.z; acc.w += val.w;
                }
#pragma unroll
                for (int off = 4; off < 32; off <<= 1) {
                    acc.x += __shfl_xor_sync(0xffffffffu, acc.x, off);
                    acc.y += __shfl_xor_sync(0xffffffffu, acc.y, off);
                    acc.z += __shfl_xor_sync(0xffffffffu, acc.z, off);
                    acc.w += __shfl_xor_sync(0xffffffffu, acc.w, off);
                }
                if (lane < 4) {
                    float inv = 1.0f / fmaxf((float)deg, 1.0f);
                    float4 xv = ((const float4*)(x + (size_t)node * IN_DIM))[lane];
                    unsigned* vp = svw + nl * V_STRIDE + lane * 4;
                    vp[0] = f2tf32(xv.x + acc.x * inv);
                    vp[1] = f2tf32(xv.y + acc.y * inv);
                    vp[2] = f2tf32(xv.z + acc.z * inv);
                    vp[3] = f2tf32(xv.w + acc.w * inv);
                }
            } else if (lane < 4) {
                unsigned* vp = svw + nl * V_STRIDE + lane * 4;
                vp[0] = vp[1] = vp[2] = vp[3] = 0u;
            }
        }
        __syncwarp();

        // ---- layer 1: h1[16,64] = relu(v @ W1 + b1) ----
        unsigned a1f[2][4];
#pragma unroll
        for (int kt = 0; kt < 2; kt++) {
            int c = kt * 8 + tg;
            a1f[kt][0] = svw[g * V_STRIDE + c];
            a1f[kt][1] = svw[(g + 8) * V_STRIDE + c];
            a1f[kt][2] = svw[g * V_STRIDE + c + 4];
            a1f[kt][3] = svw[(g + 8) * V_STRIDE + c + 4];
        }
#pragma unroll
        for (int nt = 0; nt < 8; nt++) {
            int ce = nt * 8 + 2 * tg;
            float d0 = sb1[ce], d1 = sb1[ce + 1], d2 = d0, d3 = d1;
#pragma unroll
            for (int kt = 0; kt < 2; kt++) {
                unsigned bf0 = sW1t[(kt * 8 + tg) * W_STRIDE + nt * 8 + g];
                unsigned bf1 = sW1t[(kt * 8 + tg + 4) * W_STRIDE + nt * 8 + g];
                mma_tf32(d0, d1, d2, d3,
                         a1f[kt][0], a1f[kt][1], a1f[kt][2], a1f[kt][3], bf0, bf1);
            }
            shw[g * H_STRIDE + ce]           = f2tf32(fmaxf(d0, 0.0f));
            shw[g * H_STRIDE + ce + 1]       = f2tf32(fmaxf(d1, 0.0f));
            shw[(g + 8) * H_STRIDE + ce]     = f2tf32(fmaxf(d2, 0.0f));
            shw[(g + 8) * H_STRIDE + ce + 1] = f2tf32(fmaxf(d3, 0.0f));
        }
        __syncwarp();

        // ---- layer 2 + masked mean accumulation ----
        unsigned a2f[8][4];
#pragma unroll
        for (int kt = 0; kt < 8; kt++) {
            int c = kt * 8 + tg;
            a2f[kt][0] = shw[g * H_STRIDE + c];
            a2f[kt][1] = shw[(g + 8) * H_STRIDE + c];
            a2f[kt][2] = shw[g * H_STRIDE + c + 4];
            a2f[kt][3] = shw[(g + 8) * H_STRIDE + c + 4];
        }
        float mv0 = (base + g     < n) ? 1.0f : 0.0f;
        float mv8 = (base + g + 8 < n) ? 1.0f : 0.0f;
#pragma unroll
        for (int nt = 0; nt < 8; nt++) {
            int ce = nt * 8 + 2 * tg;
            float d0 = sb2[ce], d1 = sb2[ce + 1], d2 = d0, d3 = d1;
#pragma unroll
            for (int kt = 0; kt < 8; kt++) {
                unsigned bf0 = sW2t[(kt * 8 + tg) * W_STRIDE + nt * 8 + g];
                unsigned bf1 = sW2t[(kt * 8 + tg + 4) * W_STRIDE + nt * 8 + g];
                mma_tf32(d0, d1, d2, d3,
                         a2f[kt][0], a2f[kt][1], a2f[kt][2], a2f[kt][3], bf0, bf1);
            }
            macc[2 * nt]     += mv0 * fmaxf(d0, 0.0f) + mv8 * fmaxf(d2, 0.0f);
            macc[2 * nt + 1] += mv0 * fmaxf(d1, 0.0f) + mv8 * fmaxf(d3, 0.0f);
        }
        __syncwarp();
    }

    // reduce mean partials across row-groups; lanes 0-3 hold 2 features x 8
#pragma unroll
    for (int off = 4; off < 32; off <<= 1)
#pragma unroll
        for (int i = 0; i < 16; i++)
            macc[i] += __shfl_xor_sync(0xffffffffu, macc[i], off);
    if (lane < 4) {
#pragma unroll
        for (int nt = 0; nt < 8; nt++) {
            atomicAdd(&ssum[nt * 8 + 2 * lane],     macc[2 * nt]);
            atomicAdd(&ssum[nt * 8 + 2 * lane + 1], macc[2 * nt + 1]);
        }
    }
    __syncthreads();
    if (tid < HID) atomicAdd(&g_hsum[tid], ssum[tid]);

    // ---- last-block finalize: out = tanh(mean @ Wh + bh); clean state ----
    __threadfence();
    if (tid == 0) {
        unsigned t = atomicAdd(&g_done, 1u);
        slast = (t == (unsigned)(gridDim.x - 1)) ? 1 : 0;
    }
    __syncthreads();
    if (slast) {
        __shared__ float red[HID];
        if (tid < HID) red[tid] = (g_hsum[tid] / (float)n) * Wh[tid];
        __syncthreads();
        for (int s = HID / 2; s > 0; s >>= 1) {
            if (tid < s) red[tid] += red[tid + s];
            __syncthreads();
        }
        if (tid == 0) out[0] = tanhf(red[0] + bh[0]);
        if (tid < HID) g_hsum[tid] = 0.0f;    // self-clean for next replay
        if (tid == 0) g_done = 0u;
    }
}

// ---------------------------------------------------------------------------
extern "C" void kernel_launch(void* const* d_in, const int* in_sizes, int n_in,
                              void* d_out, int out_size) {
    const float* x  = (const float*)d_in[0];
    const int*   ei = (const int*)d_in[1];
    const float* W1 = (const float*)d_in[2];
    const float* b1 = (const float*)d_in[3];
    const float* W2 = (const float*)d_in[4];
    const float* b2 = (const float*)d_in[5];
    const float* Wh = (const float*)d_in[6];
    const float* bh = (const float*)d_in[7];
    float* out = (float*)d_out;

    int n = in_sizes[0] / IN_DIM;
    int E = in_sizes[1] / 2;
    int et = (E + 3) / 4;

    scatter_kernel<<<(et + 255) / 256, 256>>>(ei, E, n);
    fused_kernel<<<GRID_BLOCKS, TB>>>(x, W1, b1, W2, b2, Wh, bh, out, n);
}

// round 10
// speedup vs baseline: 1.8484x; 1.8484x over previous
#include <cuda_runtime.h>
#include <cuda_bf16.h>
#include <math.h>

// SimpleGNN: bucket scatter + tensor-core (tf32 mma) fused agg/MLP with
// in-kernel finalize. 2 launches. Cursor self-clean is done hazard-free:
// per warp-tile, lanes 0-15 load the 16 node degrees (coalesced), the SAME
// thread stores 0 back (program-order load->store, no aliasing ambiguity),
// and the node loop reads degrees via shfl — so no cursor loads follow any
// cursor store and ptxas can pipeline the 16 node gather-chains.
//
// Inputs: x[N*16] f32, edge_index int32 (harness downcast), W1,b1,W2,b2,Wh,bh.
// Output: 1 f32.

#define MAX_NODES 100000
#define CAP       128
#define HID       64
#define IN_DIM    16
#define TB        128          // threads per block (4 warps)
#define GRID_BLOCKS 592        // ~4 blocks/SM
#define TILE      16           // nodes per warp-tile
#define W_STRIDE  72           // conflict-free B-frag rows
#define H_STRIDE  68
#define V_STRIDE  17

__device__ unsigned g_cursor[MAX_NODES];          // zero-init at load
__device__ int      g_bucket[MAX_NODES * CAP];
__device__ float    g_hsum[HID];                  // zero-init at load
__device__ unsigned g_done;                       // zero-init at load

__device__ __forceinline__ unsigned f2tf32(float f) {
    unsigned r; asm("cvt.rna.tf32.f32 %0, %1;" : "=r"(r) : "f"(f)); return r;
}

__device__ __forceinline__ void mma_tf32(float& d0, float& d1, float& d2, float& d3,
                                         unsigned a0, unsigned a1, unsigned a2, unsigned a3,
                                         unsigned b0, unsigned b1) {
    asm volatile(
        "mma.sync.aligned.m16n8k8.row.col.f32.tf32.tf32.f32 "
        "{%0,%1,%2,%3}, {%4,%5,%6,%7}, {%8,%9}, {%0,%1,%2,%3};"
        : "+f"(d0), "+f"(d1), "+f"(d2), "+f"(d3)
        : "r"(a0), "r"(a1), "r"(a2), "r"(a3), "r"(b0), "r"(b1));
}

// ---------------------------------------------------------------------------
// Scatter: 4 edges per thread; cursor atomic doubles as degree counter.
// ---------------------------------------------------------------------------
__global__ void scatter_kernel(const int* __restrict__ ei, int E, int n) {
    int t = blockIdx.x * blockDim.x + threadIdx.x;
    int base = t * 4;
    if (base >= E) return;
    int4 s4 = *(const int4*)(ei + base);
    int4 d4 = *(const int4*)(ei + E + base);
#pragma unroll
    for (int j = 0; j < 4; j++) {
        int s = (j == 0) ? s4.x : (j == 1) ? s4.y : (j == 2) ? s4.z : s4.w;
        int d = (j == 0) ? d4.x : (j == 1) ? d4.y : (j == 2) ? d4.z : d4.w;
        if ((unsigned)s < (unsigned)n) {
            unsigned slot = atomicAdd(&g_cursor[s], 1u);
            if (slot < CAP) g_bucket[(size_t)s * CAP + slot] = d;
        }
    }
}

// ---------------------------------------------------------------------------
// Fused aggregation + MMA MLP + last-block finalize + self-clean.
// ---------------------------------------------------------------------------
__global__ void __launch_bounds__(TB) fused_kernel(
    const float* __restrict__ x,
    const float* __restrict__ W1, const float* __restrict__ b1,
    const float* __restrict__ W2, const float* __restrict__ b2,
    const float* __restrict__ Wh, const float* __restrict__ bh,
    float* __restrict__ out, int n) {
    __shared__ unsigned sW1t[IN_DIM * W_STRIDE];
    __shared__ unsigned sW2t[HID * W_STRIDE];
    __shared__ float sb1[HID];
    __shared__ float sb2[HID];
    __shared__ unsigned sv[4][TILE * V_STRIDE];
    __shared__ unsigned sh1[4][TILE * H_STRIDE];
    __shared__ float ssum[HID];
    __shared__ int slast;

    int tid  = threadIdx.x;
    int wid  = tid >> 5;
    int lane = tid & 31;
    int g    = lane >> 2;     // mma groupID (row)
    int tg   = lane & 3;      // mma threadID_in_group

    for (int i = tid; i < IN_DIM * HID; i += TB) {
        int k = i >> 6, nn = i & 63;
        sW1t[k * W_STRIDE + nn] = f2tf32(W1[i]);
    }
    for (int i = tid; i < HID * HID; i += TB) {
        int k = i >> 6, nn = i & 63;
        sW2t[k * W_STRIDE + nn] = f2tf32(W2[i]);
    }
    if (tid < HID) { sb1[tid] = b1[tid]; sb2[tid] = b2[tid]; ssum[tid] = 0.0f; }
    __syncthreads();

    unsigned* svw = sv[wid];
    unsigned* shw = sh1[wid];
    float macc[16];
#pragma unroll
    for (int i = 0; i < 16; i++) macc[i] = 0.0f;

    for (int base = (blockIdx.x * 4 + wid) * TILE; base < n;
         base += GRID_BLOCKS * 4 * TILE) {

        // ---- batched degree load + same-thread clean (hazard-free) ----
        unsigned mydeg = 0u;
        if (lane < TILE && base + lane < n) {
            mydeg = g_cursor[base + lane];       // one coalesced 64B load
            g_cursor[base + lane] = 0u;          // same thread, same addr:
        }                                        // program-order safe
        __syncwarp();

        // ---- aggregate 16 nodes (4-lane teams: lane tg reads float4 #tg of
        //      row d; one warp gather instr covers 8 distinct rows) ----
        for (int nl = 0; nl < TILE; nl++) {
            int node = base + nl;
            unsigned deg = __shfl_sync(0xffffffffu, mydeg, nl);
            if (node < n) {
                unsigned lim = (deg < CAP) ? deg : CAP;
                const int* bucket = g_bucket + (size_t)node * CAP;
                float4 acc = make_float4(0.f, 0.f, 0.f, 0.f);
                for (unsigned i = (unsigned)g; i < lim; i += 8) {
                    int d = bucket[i];
                    float4 val = ((const float4*)(x + (size_t)d * IN_DIM))[tg];
                    acc.x += val.x; acc.y += val.y; acc.z += val.z; acc.w += val.w;
                }
#pragma unroll
                for (int off = 4; off < 32; off <<= 1) {
                    acc.x += __shfl_xor_sync(0xffffffffu, acc.x, off);
                    acc.y += __shfl_xor_sync(0xffffffffu, acc.y, off);
                    acc.z += __shfl_xor_sync(0xffffffffu, acc.z, off);
                    acc.w += __shfl_xor_sync(0xffffffffu, acc.w, off);
                }
                if (lane < 4) {
                    float inv = 1.0f / fmaxf((float)deg, 1.0f);
                    float4 xv = ((const float4*)(x + (size_t)node * IN_DIM))[lane];
                    unsigned* vp = svw + nl * V_STRIDE + lane * 4;
                    vp[0] = f2tf32(xv.x + acc.x * inv);
                    vp[1] = f2tf32(xv.y + acc.y * inv);
                    vp[2] = f2tf32(xv.z + acc.z * inv);
                    vp[3] = f2tf32(xv.w + acc.w * inv);
                }
            } else if (lane < 4) {
                unsigned* vp = svw + nl * V_STRIDE + lane * 4;
                vp[0] = vp[1] = vp[2] = vp[3] = 0u;
            }
        }
        __syncwarp();

        // ---- layer 1: h1[16,64] = relu(v @ W1 + b1) ----
        unsigned a1f[2][4];
#pragma unroll
        for (int kt = 0; kt < 2; kt++) {
            int c = kt * 8 + tg;
            a1f[kt][0] = svw[g * V_STRIDE + c];
            a1f[kt][1] = svw[(g + 8) * V_STRIDE + c];
            a1f[kt][2] = svw[g * V_STRIDE + c + 4];
            a1f[kt][3] = svw[(g + 8) * V_STRIDE + c + 4];
        }
#pragma unroll
        for (int nt = 0; nt < 8; nt++) {
            int ce = nt * 8 + 2 * tg;
            float d0 = sb1[ce], d1 = sb1[ce + 1], d2 = d0, d3 = d1;
#pragma unroll
            for (int kt = 0; kt < 2; kt++) {
                unsigned bf0 = sW1t[(kt * 8 + tg) * W_STRIDE + nt * 8 + g];
                unsigned bf1 = sW1t[(kt * 8 + tg + 4) * W_STRIDE + nt * 8 + g];
                mma_tf32(d0, d1, d2, d3,
                         a1f[kt][0], a1f[kt][1], a1f[kt][2], a1f[kt][3], bf0, bf1);
            }
            shw[g * H_STRIDE + ce]           = f2tf32(fmaxf(d0, 0.0f));
            shw[g * H_STRIDE + ce + 1]       = f2tf32(fmaxf(d1, 0.0f));
            shw[(g + 8) * H_STRIDE + ce]     = f2tf32(fmaxf(d2, 0.0f));
            shw[(g + 8) * H_STRIDE + ce + 1] = f2tf32(fmaxf(d3, 0.0f));
        }
        __syncwarp();

        // ---- layer 2 + masked mean accumulation ----
        unsigned a2f[8][4];
#pragma unroll
        for (int kt = 0; kt < 8; kt++) {
            int c = kt * 8 + tg;
            a2f[kt][0] = shw[g * H_STRIDE + c];
            a2f[kt][1] = shw[(g + 8) * H_STRIDE + c];
            a2f[kt][2] = shw[g * H_STRIDE + c + 4];
            a2f[kt][3] = shw[(g + 8) * H_STRIDE + c + 4];
        }
        float mv0 = (base + g     < n) ? 1.0f : 0.0f;
        float mv8 = (base + g + 8 < n) ? 1.0f : 0.0f;
#pragma unroll
        for (int nt = 0; nt < 8; nt++) {
            int ce = nt * 8 + 2 * tg;
            float d0 = sb2[ce], d1 = sb2[ce + 1], d2 = d0, d3 = d1;
#pragma unroll
            for (int kt = 0; kt < 8; kt++) {
                unsigned bf0 = sW2t[(kt * 8 + tg) * W_STRIDE + nt * 8 + g];
                unsigned bf1 = sW2t[(kt * 8 + tg + 4) * W_STRIDE + nt * 8 + g];
                mma_tf32(d0, d1, d2, d3,
                         a2f[kt][0], a2f[kt][1], a2f[kt][2], a2f[kt][3], bf0, bf1);
            }
            macc[2 * nt]     += mv0 * fmaxf(d0, 0.0f) + mv8 * fmaxf(d2, 0.0f);
            macc[2 * nt + 1] += mv0 * fmaxf(d1, 0.0f) + mv8 * fmaxf(d3, 0.0f);
        }
        __syncwarp();
    }

    // reduce mean partials across row-groups; lanes 0-3 hold 2 features x 8
#pragma unroll
    for (int off = 4; off < 32; off <<= 1)
#pragma unroll
        for (int i = 0; i < 16; i++)
            macc[i] += __shfl_xor_sync(0xffffffffu, macc[i], off);
    if (lane < 4) {
#pragma unroll
        for (int nt = 0; nt < 8; nt++) {
            atomicAdd(&ssum[nt * 8 + 2 * lane],     macc[2 * nt]);
            atomicAdd(&ssum[nt * 8 + 2 * lane + 1], macc[2 * nt + 1]);
        }
    }
    __syncthreads();
    if (tid < HID) atomicAdd(&g_hsum[tid], ssum[tid]);

    // ---- last-block finalize: out = tanh(mean @ Wh + bh); clean state ----
    __threadfence();
    if (tid == 0) {
        unsigned t = atomicAdd(&g_done, 1u);
        slast = (t == (unsigned)(gridDim.x - 1)) ? 1 : 0;
    }
    __syncthreads();
    if (slast) {
        __shared__ float red[HID];
        if (tid < HID) red[tid] = (g_hsum[tid] / (float)n) * Wh[tid];
        __syncthreads();
        for (int s = HID / 2; s > 0; s >>= 1) {
            if (tid < s) red[tid] += red[tid + s];
            __syncthreads();
        }
        if (tid == 0) out[0] = tanhf(red[0] + bh[0]);
        if (tid < HID) g_hsum[tid] = 0.0f;    // self-clean for next replay
        if (tid == 0) g_done = 0u;
    }
}

// ---------------------------------------------------------------------------
extern "C" void kernel_launch(void* const* d_in, const int* in_sizes, int n_in,
                              void* d_out, int out_size) {
    const float* x  = (const float*)d_in[0];
    const int*   ei = (const int*)d_in[1];
    const float* W1 = (const float*)d_in[2];
    const float* b1 = (const float*)d_in[3];
    const float* W2 = (const float*)d_in[4];
    const float* b2 = (const float*)d_in[5];
    const float* Wh = (const float*)d_in[6];
    const float* bh = (const float*)d_in[7];
    float* out = (float*)d_out;

    int n = in_sizes[0] / IN_DIM;
    int E = in_sizes[1] / 2;
    int et = (E + 3) / 4;

    scatter_kernel<<<(et + 255) / 256, 256>>>(ei, E, n);
    fused_kernel<<<GRID_BLOCKS, TB>>>(x, W1, b1, W2, b2, Wh, bh, out, n);
}